// round 4
// baseline (speedup 1.0000x reference)
#include <cuda_runtime.h>
#include <cstdint>

#define D_DIM   512
#define K_DIM   112
#define BM      256
#define BK      16
#define NTHR    224              // 14 colgroups x 16 rowgroups
#define XSP     260              // x tile stride (floats), 16B aligned
#define CSP     116              // C tile stride
#define SIMSP   114              // even -> 8B-aligned ull stores
#define LAMBDA_ 5.0f

#define XS_FLOATS   (BK * XSP)                    // 4160
#define CS_OFF      XS_FLOATS
#define CS_FLOATS   (BK * CSP)                    // 1856
#define SIMS_FLOATS (BM * SIMSP)                  // 29184
#define W5_OFF      SIMS_FLOATS
#define I5_OFF      (SIMS_FLOATS + BM * 5)
#define SMEM_FLOATS (SIMS_FLOATS + BM * 5 * 2)    // 31744
#define SMEM_BYTES  (SMEM_FLOATS * 4)             // 126976

__device__ __forceinline__ unsigned long long fma2(unsigned long long a,
                                                   unsigned long long b,
                                                   unsigned long long c) {
    unsigned long long d;
    asm("fma.rn.f32x2 %0, %1, %2, %3;" : "=l"(d) : "l"(a), "l"(b), "l"(c));
    return d;
}
__device__ __forceinline__ unsigned long long dup2(float a) {
    unsigned long long r;
    asm("mov.b64 %0, {%1, %1};" : "=l"(r) : "f"(a));
    return r;
}

__global__ __launch_bounds__(NTHR, 1)
void tse_gemm16_kernel(const float* __restrict__ x,
                       const float* __restrict__ cc,
                       float* __restrict__ out)
{
    extern __shared__ float sm[];
    float* xs = sm;                  // [BK][XSP] depth-major x tile
    float* cs = sm + CS_OFF;         // [BK][CSP] depth-major C tile

    const int tid = threadIdx.x;
    const int cg  = tid / 16;        // 0..13  -> cols cg*8 .. cg*8+7
    const int rg  = tid % 16;        // 0..15  -> rows rg*16 .. rg*16+15
    const int row0 = blockIdx.x * BM;

    unsigned long long acc[16][4];
    #pragma unroll
    for (int i = 0; i < 16; i++)
        #pragma unroll
        for (int j = 0; j < 4; j++) acc[i][j] = 0ull;

    // ---- register prefetch buffers ----
    // x tile: BM*BK/4 = 1024 quads; C tile: K_DIM*BK/4 = 448 quads
    float4 px[5], pc[2];

    auto FETCH = [&](int kb) {
        #pragma unroll
        for (int i = 0; i < 5; i++) {
            int gid = tid + NTHR * i;
            if (i < 4 || gid < 1024) {
                int r = gid >> 2, dq = (gid & 3) << 2;
                px[i] = *(const float4*)&x[(size_t)(row0 + r) * D_DIM + kb * BK + dq];
            }
        }
        #pragma unroll
        for (int i = 0; i < 2; i++) {
            int gid = tid + NTHR * i;           // < 448 always
            int c = gid >> 2, dq = (gid & 3) << 2;
            pc[i] = *(const float4*)&cc[(size_t)c * D_DIM + kb * BK + dq];
        }
    };

    auto STORE = [&]() {
        #pragma unroll
        for (int i = 0; i < 5; i++) {
            int gid = tid + NTHR * i;
            if (i < 4 || gid < 1024) {
                int r = gid >> 2, dq = (gid & 3) << 2;
                xs[(dq + 0) * XSP + r] = px[i].x;
                xs[(dq + 1) * XSP + r] = px[i].y;
                xs[(dq + 2) * XSP + r] = px[i].z;
                xs[(dq + 3) * XSP + r] = px[i].w;
            }
        }
        #pragma unroll
        for (int i = 0; i < 2; i++) {
            int gid = tid + NTHR * i;
            int c = gid >> 2, dq = (gid & 3) << 2;
            cs[(dq + 0) * CSP + c] = pc[i].x;
            cs[(dq + 1) * CSP + c] = pc[i].y;
            cs[(dq + 2) * CSP + c] = pc[i].z;
            cs[(dq + 3) * CSP + c] = pc[i].w;
        }
    };

    FETCH(0);
    for (int kb = 0; kb < D_DIM / BK; kb++) {
        __syncthreads();
        STORE();
        __syncthreads();
        if (kb + 1 < D_DIM / BK) FETCH(kb + 1);   // overlap LDG with compute

        #pragma unroll
        for (int kk = 0; kk < BK; kk++) {
            const float* xr = &xs[kk * XSP + rg * 16];
            float4 xa = *(const float4*)(xr + 0);
            float4 xb = *(const float4*)(xr + 4);
            float4 xc = *(const float4*)(xr + 8);
            float4 xd = *(const float4*)(xr + 12);
            ulonglong2 cv0 = *(const ulonglong2*)&cs[kk * CSP + cg * 8];
            ulonglong2 cv1 = *(const ulonglong2*)&cs[kk * CSP + cg * 8 + 4];
            unsigned long long b0 = cv0.x, b1 = cv0.y, b2 = cv1.x, b3 = cv1.y;

            float xv[16] = {xa.x,xa.y,xa.z,xa.w, xb.x,xb.y,xb.z,xb.w,
                            xc.x,xc.y,xc.z,xc.w, xd.x,xd.y,xd.z,xd.w};
            #pragma unroll
            for (int r = 0; r < 16; r++) {
                unsigned long long a = dup2(xv[r]);
                acc[r][0] = fma2(a, b0, acc[r][0]);
                acc[r][1] = fma2(a, b1, acc[r][1]);
                acc[r][2] = fma2(a, b2, acc[r][2]);
                acc[r][3] = fma2(a, b3, acc[r][3]);
            }
        }
    }

    // ---- dump sims to SMEM (overlay tiles) ----
    __syncthreads();
    float* sims = sm;
    #pragma unroll
    for (int r = 0; r < 16; r++) {
        int row = rg * 16 + r;
        #pragma unroll
        for (int j = 0; j < 4; j++) {
            // little-endian: low word = col (cg*8+2j), high = +1  (matches cs pairs)
            *(unsigned long long*)&sims[row * SIMSP + cg * 8 + 2 * j] = acc[r][j];
        }
    }
    __syncthreads();

    // ---- per-row top-5 + softmax ----
    float* w5 = sm + W5_OFF;
    int*   i5 = (int*)(sm + I5_OFF);
    for (int r = tid; r < BM; r += NTHR) {
        const float* sr = &sims[r * SIMSP];
        float v0 = -1e30f, v1 = -1e30f, v2 = -1e30f, v3 = -1e30f, v4 = -1e30f;
        int   i0 = 0, i1 = 0, i2 = 0, i3 = 0, i4 = 0;
        for (int c = 0; c < K_DIM; c++) {
            float s = sr[c];
            if (s > v4) {                       // strict >: earliest index wins ties
                v4 = s; i4 = c;
                if (v4 > v3) { float t=v3; v3=v4; v4=t; int ti=i3; i3=i4; i4=ti; }
                if (v3 > v2) { float t=v2; v2=v3; v3=t; int ti=i2; i2=i3; i3=ti; }
                if (v2 > v1) { float t=v1; v1=v2; v2=t; int ti=i1; i1=i2; i2=ti; }
                if (v1 > v0) { float t=v0; v0=v1; v1=t; int ti=i0; i0=i1; i1=ti; }
            }
        }
        float e1 = __expf(v1 - v0);
        float e2 = __expf(v2 - v0);
        float e3 = __expf(v3 - v0);
        float e4 = __expf(v4 - v0);
        float inv = LAMBDA_ / (1.0f + e1 + e2 + e3 + e4);
        w5[r * 5 + 0] = inv;       i5[r * 5 + 0] = i0;
        w5[r * 5 + 1] = e1 * inv;  i5[r * 5 + 1] = i1;
        w5[r * 5 + 2] = e2 * inv;  i5[r * 5 + 2] = i2;
        w5[r * 5 + 3] = e3 * inv;  i5[r * 5 + 3] = i3;
        w5[r * 5 + 4] = e4 * inv;  i5[r * 5 + 4] = i4;
    }
    __syncthreads();

    // ---- epilogue: out = x + sum w_j * C[idx_j]  (2 units per row) ----
    for (int u = tid; u < BM * 2; u += NTHR) {
        int r = u >> 1, h = u & 1;
        float w0 = w5[r*5+0], w1 = w5[r*5+1], w2 = w5[r*5+2], w3 = w5[r*5+3], w4 = w5[r*5+4];
        int   j0 = i5[r*5+0], j1 = i5[r*5+1], j2 = i5[r*5+2], j3 = i5[r*5+3], j4 = i5[r*5+4];

        size_t grow = (size_t)(row0 + r) * D_DIM + h * 256;
        const float4* xp = (const float4*)&x[grow];
        float4*       op = (float4*)&out[grow];
        const float4* c0 = (const float4*)&cc[(size_t)j0 * D_DIM + h * 256];
        const float4* c1 = (const float4*)&cc[(size_t)j1 * D_DIM + h * 256];
        const float4* c2 = (const float4*)&cc[(size_t)j2 * D_DIM + h * 256];
        const float4* c3 = (const float4*)&cc[(size_t)j3 * D_DIM + h * 256];
        const float4* c4 = (const float4*)&cc[(size_t)j4 * D_DIM + h * 256];

        #pragma unroll 4
        for (int q = 0; q < 64; q++) {
            float4 xv = xp[q];
            float4 a0 = c0[q], a1 = c1[q], a2 = c2[q], a3 = c3[q], a4 = c4[q];
            float4 o;
            o.x = xv.x + w0*a0.x + w1*a1.x + w2*a2.x + w3*a3.x + w4*a4.x;
            o.y = xv.y + w0*a0.y + w1*a1.y + w2*a2.y + w3*a3.y + w4*a4.y;
            o.z = xv.z + w0*a0.z + w1*a1.z + w2*a2.z + w3*a3.z + w4*a4.z;
            o.w = xv.w + w0*a0.w + w1*a1.w + w2*a2.w + w3*a3.w + w4*a4.w;
            op[q] = o;
        }
    }
}

extern "C" void kernel_launch(void* const* d_in, const int* in_sizes, int n_in,
                              void* d_out, int out_size)
{
    const float* x  = (const float*)d_in[0];
    const float* cc = (const float*)d_in[1];
    int B = in_sizes[0] / D_DIM;

    cudaFuncSetAttribute(tse_gemm16_kernel, cudaFuncAttributeMaxDynamicSharedMemorySize, SMEM_BYTES);

    int grid = B / BM;               // 512 for B=131072
    tse_gemm16_kernel<<<grid, NTHR, SMEM_BYTES>>>(x, cc, (float*)d_out);
}

// round 5
// speedup vs baseline: 1.4944x; 1.4944x over previous
#include <cuda_runtime.h>
#include <cstdint>

#define D_DIM   512
#define K_DIM   112
#define BM      128
#define BK      16
#define NTHR    224              // 14 colgroups x 16 rowgroups
#define XSP     132              // x tile stride (floats): 528B, 16B-aligned
#define CSP     116              // C tile stride: 464B, 16B-aligned
#define SIMSP   114              // even -> 8B-aligned ull stores
#define LAMBDA_ 5.0f

#define CS_OFF      (BK * XSP)                    // 2112 floats
#define GEMM_FLOATS (BK * XSP + BK * CSP)         // 3968
#define SIMS_FLOATS (BM * SIMSP)                  // 14592
#define W5_OFF      SIMS_FLOATS
#define I5_OFF      (SIMS_FLOATS + BM * 5)
#define SMEM_FLOATS (SIMS_FLOATS + BM * 5 * 2)    // 15872
#define SMEM_BYTES  (SMEM_FLOATS * 4)             // 63488

__device__ __forceinline__ unsigned long long fma2(unsigned long long a,
                                                   unsigned long long b,
                                                   unsigned long long c) {
    unsigned long long d;
    asm("fma.rn.f32x2 %0, %1, %2, %3;" : "=l"(d) : "l"(a), "l"(b), "l"(c));
    return d;
}
__device__ __forceinline__ unsigned long long dup2(float a) {
    unsigned long long r;
    asm("mov.b64 %0, {%1, %1};" : "=l"(r) : "f"(a));
    return r;
}

__global__ __launch_bounds__(NTHR, 2)
void tse_gemm8x8_kernel(const float* __restrict__ x,
                        const float* __restrict__ cc,
                        float* __restrict__ out)
{
    extern __shared__ float sm[];
    float* xs = sm;                  // [BK][XSP] depth-major x tile
    float* cs = sm + CS_OFF;         // [BK][CSP] depth-major C tile

    const int tid = threadIdx.x;
    const int cg  = tid >> 4;        // 0..13 -> cols cg*8..cg*8+7
    const int rg  = tid & 15;        // 0..15 -> rows rg*4..+3 and 64+rg*4..+3
    const int row0 = blockIdx.x * BM;

    unsigned long long acc[2][4][4]; // [half][row-in-frag][colpair]
    #pragma unroll
    for (int h = 0; h < 2; h++)
        #pragma unroll
        for (int i = 0; i < 4; i++)
            #pragma unroll
            for (int j = 0; j < 4; j++) acc[h][i][j] = 0ull;

    // register prefetch: x tile 128*4=512 quads, C tile 112*4=448 quads
    float4 px[3], pc[2];

    auto FETCH = [&](int kb) {
        #pragma unroll
        for (int i = 0; i < 3; i++) {
            int gid = tid + NTHR * i;
            if (i < 2 || gid < 512) {
                int r = gid >> 2, dq = (gid & 3) << 2;
                px[i] = *(const float4*)&x[(size_t)(row0 + r) * D_DIM + kb * BK + dq];
            }
        }
        #pragma unroll
        for (int i = 0; i < 2; i++) {
            int gid = tid + NTHR * i;                 // < 448
            int c = gid >> 2, dq = (gid & 3) << 2;
            pc[i] = *(const float4*)&cc[(size_t)c * D_DIM + kb * BK + dq];
        }
    };

    auto STORE = [&]() {
        #pragma unroll
        for (int i = 0; i < 3; i++) {
            int gid = tid + NTHR * i;
            if (i < 2 || gid < 512) {
                int r = gid >> 2, dq = (gid & 3) << 2;
                xs[(dq + 0) * XSP + r] = px[i].x;
                xs[(dq + 1) * XSP + r] = px[i].y;
                xs[(dq + 2) * XSP + r] = px[i].z;
                xs[(dq + 3) * XSP + r] = px[i].w;
            }
        }
        #pragma unroll
        for (int i = 0; i < 2; i++) {
            int gid = tid + NTHR * i;
            int c = gid >> 2, dq = (gid & 3) << 2;
            cs[(dq + 0) * CSP + c] = pc[i].x;
            cs[(dq + 1) * CSP + c] = pc[i].y;
            cs[(dq + 2) * CSP + c] = pc[i].z;
            cs[(dq + 3) * CSP + c] = pc[i].w;
        }
    };

    FETCH(0);
    for (int kb = 0; kb < D_DIM / BK; kb++) {
        __syncthreads();
        STORE();
        __syncthreads();
        if (kb + 1 < D_DIM / BK) FETCH(kb + 1);   // LDG overlaps compute

        #pragma unroll
        for (int kk = 0; kk < BK; kk++) {
            // conflict-free LDS.128s: rg*16B contiguous across the phase
            float4 xa = *(const float4*)&xs[kk * XSP + rg * 4];
            float4 xb = *(const float4*)&xs[kk * XSP + 64 + rg * 4];
            ulonglong2 cv0 = *(const ulonglong2*)&cs[kk * CSP + cg * 8];     // LDS.128
            ulonglong2 cv1 = *(const ulonglong2*)&cs[kk * CSP + cg * 8 + 4]; // LDS.128
            unsigned long long b0 = cv0.x, b1 = cv0.y, b2 = cv1.x, b3 = cv1.y;

            float va[4] = {xa.x, xa.y, xa.z, xa.w};
            float vb[4] = {xb.x, xb.y, xb.z, xb.w};
            #pragma unroll
            for (int r = 0; r < 4; r++) {
                unsigned long long a = dup2(va[r]);
                acc[0][r][0] = fma2(a, b0, acc[0][r][0]);
                acc[0][r][1] = fma2(a, b1, acc[0][r][1]);
                acc[0][r][2] = fma2(a, b2, acc[0][r][2]);
                acc[0][r][3] = fma2(a, b3, acc[0][r][3]);
            }
            #pragma unroll
            for (int r = 0; r < 4; r++) {
                unsigned long long a = dup2(vb[r]);
                acc[1][r][0] = fma2(a, b0, acc[1][r][0]);
                acc[1][r][1] = fma2(a, b1, acc[1][r][1]);
                acc[1][r][2] = fma2(a, b2, acc[1][r][2]);
                acc[1][r][3] = fma2(a, b3, acc[1][r][3]);
            }
        }
    }

    // ---- dump sims to SMEM (overlay tiles) ----
    __syncthreads();
    float* sims = sm;
    #pragma unroll
    for (int h = 0; h < 2; h++)
        #pragma unroll
        for (int r = 0; r < 4; r++) {
            int row = h * 64 + rg * 4 + r;
            #pragma unroll
            for (int j = 0; j < 4; j++)
                *(unsigned long long*)&sims[row * SIMSP + cg * 8 + 2 * j] = acc[h][r][j];
        }
    __syncthreads();

    // ---- per-row top-5 + softmax ----
    float* w5 = sm + W5_OFF;
    int*   i5 = (int*)(sm + I5_OFF);
    if (tid < BM) {
        const float* sr = &sims[tid * SIMSP];
        float v0 = -1e30f, v1 = -1e30f, v2 = -1e30f, v3 = -1e30f, v4 = -1e30f;
        int   i0 = 0, i1 = 0, i2 = 0, i3 = 0, i4 = 0;
        for (int c = 0; c < K_DIM; c++) {
            float s = sr[c];
            if (s > v4) {                           // strict >: earliest index wins ties
                v4 = s; i4 = c;
                if (v4 > v3) { float t=v3; v3=v4; v4=t; int ti=i3; i3=i4; i4=ti; }
                if (v3 > v2) { float t=v2; v2=v3; v3=t; int ti=i2; i2=i3; i3=ti; }
                if (v2 > v1) { float t=v1; v1=v2; v2=t; int ti=i1; i1=i2; i2=ti; }
                if (v1 > v0) { float t=v0; v0=v1; v1=t; int ti=i0; i0=i1; i1=ti; }
            }
        }
        float e1 = __expf(v1 - v0);
        float e2 = __expf(v2 - v0);
        float e3 = __expf(v3 - v0);
        float e4 = __expf(v4 - v0);
        float inv = LAMBDA_ / (1.0f + e1 + e2 + e3 + e4);
        w5[tid * 5 + 0] = inv;       i5[tid * 5 + 0] = i0;
        w5[tid * 5 + 1] = e1 * inv;  i5[tid * 5 + 1] = i1;
        w5[tid * 5 + 2] = e2 * inv;  i5[tid * 5 + 2] = i2;
        w5[tid * 5 + 3] = e3 * inv;  i5[tid * 5 + 3] = i3;
        w5[tid * 5 + 4] = e4 * inv;  i5[tid * 5 + 4] = i4;
    }
    __syncthreads();

    // ---- epilogue: out = x + sum w_j * C[idx_j]  (2 half-row units per row) ----
    for (int u = tid; u < BM * 2; u += NTHR) {
        int r = u >> 1, h = u & 1;
        float w0 = w5[r*5+0], w1 = w5[r*5+1], w2 = w5[r*5+2], w3 = w5[r*5+3], w4 = w5[r*5+4];
        int   j0 = i5[r*5+0], j1 = i5[r*5+1], j2 = i5[r*5+2], j3 = i5[r*5+3], j4 = i5[r*5+4];

        size_t grow = (size_t)(row0 + r) * D_DIM + h * 256;
        const float4* xp = (const float4*)&x[grow];
        float4*       op = (float4*)&out[grow];
        const float4* c0 = (const float4*)&cc[(size_t)j0 * D_DIM + h * 256];
        const float4* c1 = (const float4*)&cc[(size_t)j1 * D_DIM + h * 256];
        const float4* c2 = (const float4*)&cc[(size_t)j2 * D_DIM + h * 256];
        const float4* c3 = (const float4*)&cc[(size_t)j3 * D_DIM + h * 256];
        const float4* c4 = (const float4*)&cc[(size_t)j4 * D_DIM + h * 256];

        #pragma unroll 4
        for (int q = 0; q < 64; q++) {
            float4 xv = xp[q];
            float4 a0 = c0[q], a1 = c1[q], a2 = c2[q], a3 = c3[q], a4 = c4[q];
            float4 o;
            o.x = xv.x + w0*a0.x + w1*a1.x + w2*a2.x + w3*a3.x + w4*a4.x;
            o.y = xv.y + w0*a0.y + w1*a1.y + w2*a2.y + w3*a3.y + w4*a4.y;
            o.z = xv.z + w0*a0.z + w1*a1.z + w2*a2.z + w3*a3.z + w4*a4.z;
            o.w = xv.w + w0*a0.w + w1*a1.w + w2*a2.w + w3*a3.w + w4*a4.w;
            op[q] = o;
        }
    }
}

extern "C" void kernel_launch(void* const* d_in, const int* in_sizes, int n_in,
                              void* d_out, int out_size)
{
    const float* x  = (const float*)d_in[0];
    const float* cc = (const float*)d_in[1];
    int B = in_sizes[0] / D_DIM;

    cudaFuncSetAttribute(tse_gemm8x8_kernel, cudaFuncAttributeMaxDynamicSharedMemorySize, SMEM_BYTES);

    int grid = B / BM;               // 1024 for B=131072
    tse_gemm8x8_kernel<<<grid, NTHR, SMEM_BYTES>>>(x, cc, (float*)d_out);
}

// round 7
// speedup vs baseline: 1.9175x; 1.2831x over previous
#include <cuda_runtime.h>
#include <cuda_fp16.h>
#include <cstdint>

#define D_DIM   512
#define K_DIM   112
#define BM      128
#define CH_K    16
#define NCH     32            // D / CH_K
#define NTHR    256
#define LAMBDA_ 5.0f

// smem byte offsets (stage overlays sims region)
#define AH_OFF   0
#define AL_OFF   6144         // 128 rows * 48B
#define BH_OFF   12288
#define BL_OFF   17664        // 112 rows * 48B after BH
#define SIMSP    114          // floats per sims row
#define SIMS_B   (BM * SIMSP * 4)          // 58368
#define W5_OFF   SIMS_B
#define I5_OFF   (W5_OFF + BM * 5 * 4)
#define SMEM_BYTES (I5_OFF + BM * 5 * 4)   // 63488

__device__ __align__(16) unsigned int g_ch[NCH * K_DIM * 8];   // [chunk][n][8 x u32(h2)]
__device__ __align__(16) unsigned int g_cl[NCH * K_DIM * 8];

__device__ __forceinline__ uint32_t smem_u32(const void* p) {
    uint32_t a;
    asm("{ .reg .u64 t; cvta.to.shared.u64 t, %1; cvt.u32.u64 %0, t; }" : "=r"(a) : "l"(p));
    return a;
}

__device__ __forceinline__ void splith(float a, float b, uint32_t& hi, uint32_t& lo) {
    __half2 h = __floats2half2_rn(a, b);
    float2  f = __half22float2(h);
    __half2 l = __floats2half2_rn(a - f.x, b - f.y);
    hi = *(uint32_t*)&h;
    lo = *(uint32_t*)&l;
}

#define LDSM4(r0, r1, r2, r3, addr) \
    asm volatile("ldmatrix.sync.aligned.m8n8.x4.shared.b16 {%0,%1,%2,%3}, [%4];" \
                 : "=r"(r0), "=r"(r1), "=r"(r2), "=r"(r3) : "r"(addr))

#define MMA(d, a0, a1, a2, a3, b0, b1) \
    asm volatile("mma.sync.aligned.m16n8k16.row.col.f32.f16.f16.f32 " \
                 "{%0,%1,%2,%3}, {%4,%5,%6,%7}, {%8,%9}, {%0,%1,%2,%3};" \
                 : "+f"((d)[0]), "+f"((d)[1]), "+f"((d)[2]), "+f"((d)[3]) \
                 : "r"(a0), "r"(a1), "r"(a2), "r"(a3), "r"(b0), "r"(b1))

// ---- pre-kernel: split cluster centers into fp16 hi/lo, chunk-major ----
__global__ void cc_split_kernel(const float* __restrict__ cc) {
    int n = blockIdx.x;                  // 0..111
    int t = threadIdx.x;                 // 0..255 : k-pair index
    float2 v = ((const float2*)cc)[n * 256 + t];
    uint32_t hi, lo;
    splith(v.x, v.y, hi, lo);
    int chunk = t >> 3, slot = t & 7;
    g_ch[chunk * (K_DIM * 8) + n * 8 + slot] = hi;
    g_cl[chunk * (K_DIM * 8) + n * 8 + slot] = lo;
}

__global__ __launch_bounds__(NTHR, 2)
void tse_hmma_kernel(const float* __restrict__ x,
                     const float* __restrict__ cc,
                     float* __restrict__ out)
{
    extern __shared__ unsigned char smem[];
    const uint32_t sb = smem_u32(smem);
    const int tid = threadIdx.x;
    const int w   = tid >> 5;
    const int l   = tid & 31;
    const int row0 = blockIdx.x * BM;

    float d[14][4];
    #pragma unroll
    for (int n = 0; n < 14; n++)
        #pragma unroll
        for (int j = 0; j < 4; j++) d[n][j] = 0.0f;

    // ldmatrix source addresses
    const uint32_t aAddrH = sb + AH_OFF + (uint32_t)(w * 16 + (l & 15)) * 48 + ((l >> 4) << 4);
    const uint32_t aAddrL = aAddrH + (AL_OFF - AH_OFF);
    const int bRow  = (l & 7) + ((l & 16) >> 1);
    const uint32_t bAddrH = sb + BH_OFF + (uint32_t)bRow * 48 + ((l & 8) << 1);

    // conversion / staging mapping
    const int cr = tid >> 1, chf = tid & 1;
    const float4* __restrict__ xsrc =
        (const float4*)&x[(size_t)(row0 + cr) * D_DIM + chf * 8];
    const uint4* __restrict__ gch4 = (const uint4*)g_ch;
    const uint4* __restrict__ gcl4 = (const uint4*)g_cl;

    float4 xv0, xv1;
    uint4  cvh, cvl;
    uint4  XH, XL;

    auto FETCH = [&](int c) {
        xv0 = xsrc[c * 4];
        xv1 = xsrc[c * 4 + 1];
        if (tid < 224) {
            cvh = gch4[c * 224 + tid];
            cvl = gcl4[c * 224 + tid];
        }
    };
    auto CONV = [&]() {
        splith(xv0.x, xv0.y, XH.x, XL.x);
        splith(xv0.z, xv0.w, XH.y, XL.y);
        splith(xv1.x, xv1.y, XH.z, XL.z);
        splith(xv1.z, xv1.w, XH.w, XL.w);
    };
    auto STORE = [&]() {
        *(uint4*)(smem + AH_OFF + cr * 48 + chf * 16) = XH;
        *(uint4*)(smem + AL_OFF + cr * 48 + chf * 16) = XL;
        if (tid < 224) {
            int r = tid >> 1, h = tid & 1;
            *(uint4*)(smem + BH_OFF + r * 48 + h * 16) = cvh;
            *(uint4*)(smem + BL_OFF + r * 48 + h * 16) = cvl;
        }
    };

    FETCH(0);
    CONV();
    for (int c = 0; c < NCH; c++) {
        __syncthreads();
        STORE();
        __syncthreads();
        if (c + 1 < NCH) FETCH(c + 1);

        uint32_t ah0, ah1, ah2, ah3, al0, al1, al2, al3;
        LDSM4(ah0, ah1, ah2, ah3, aAddrH);
        LDSM4(al0, al1, al2, al3, aAddrL);
        #pragma unroll
        for (int p = 0; p < 7; p++) {
            uint32_t bh0, bh1, bh2, bh3, bl0, bl1, bl2, bl3;
            LDSM4(bh0, bh1, bh2, bh3, bAddrH + p * 768);
            MMA(d[2*p],   ah0, ah1, ah2, ah3, bh0, bh1);
            MMA(d[2*p+1], ah0, ah1, ah2, ah3, bh2, bh3);
            MMA(d[2*p],   al0, al1, al2, al3, bh0, bh1);
            MMA(d[2*p+1], al0, al1, al2, al3, bh2, bh3);
            LDSM4(bl0, bl1, bl2, bl3, bAddrH + p * 768 + (BL_OFF - BH_OFF));
            MMA(d[2*p],   ah0, ah1, ah2, ah3, bl0, bl1);
            MMA(d[2*p+1], ah0, ah1, ah2, ah3, bl2, bl3);
        }
        if (c + 1 < NCH) CONV();
    }

    // ---- dump sims to smem (overlays stage buffers) ----
    __syncthreads();
    float* sims = (float*)smem;
    {
        int r1 = w * 16 + (l >> 2);
        int r2 = r1 + 8;
        int c0 = (l & 3) * 2;
        #pragma unroll
        for (int n = 0; n < 14; n++) {
            *(float2*)&sims[r1 * SIMSP + n * 8 + c0] = make_float2(d[n][0], d[n][1]);
            *(float2*)&sims[r2 * SIMSP + n * 8 + c0] = make_float2(d[n][2], d[n][3]);
        }
    }
    __syncthreads();

    // ---- per-row top-5 + softmax ----
    float* w5 = (float*)(smem + W5_OFF);
    int*   i5 = (int*)(smem + I5_OFF);
    if (tid < BM) {
        const float* sr = &sims[tid * SIMSP];
        float v0 = -1e30f, v1 = -1e30f, v2 = -1e30f, v3 = -1e30f, v4 = -1e30f;
        int   i0 = 0, i1 = 0, i2 = 0, i3 = 0, i4 = 0;
        for (int c = 0; c < K_DIM; c++) {
            float s = sr[c];
            if (s > v4) {                       // strict >: earliest index wins ties
                v4 = s; i4 = c;
                if (v4 > v3) { float t=v3; v3=v4; v4=t; int q=i3; i3=i4; i4=q; }
                if (v3 > v2) { float t=v2; v2=v3; v3=t; int q=i2; i2=i3; i3=q; }
                if (v2 > v1) { float t=v1; v1=v2; v2=t; int q=i1; i1=i2; i2=q; }
                if (v1 > v0) { float t=v0; v0=v1; v1=t; int q=i0; i0=i1; i1=q; }
            }
        }
        float e1 = __expf(v1 - v0);
        float e2 = __expf(v2 - v0);
        float e3 = __expf(v3 - v0);
        float e4 = __expf(v4 - v0);
        float inv = LAMBDA_ / (1.0f + e1 + e2 + e3 + e4);
        w5[tid*5+0] = inv;      i5[tid*5+0] = i0;
        w5[tid*5+1] = e1 * inv; i5[tid*5+1] = i1;
        w5[tid*5+2] = e2 * inv; i5[tid*5+2] = i2;
        w5[tid*5+3] = e3 * inv; i5[tid*5+3] = i3;
        w5[tid*5+4] = e4 * inv; i5[tid*5+4] = i4;
    }
    __syncthreads();

    // ---- epilogue: out = x + sum w_j * C[idx_j]  (one half-row per thread) ----
    {
        int r = tid >> 1, h = tid & 1;
        float w0 = w5[r*5+0], w1 = w5[r*5+1], w2 = w5[r*5+2], w3 = w5[r*5+3], w4 = w5[r*5+4];
        int   j0 = i5[r*5+0], j1 = i5[r*5+1], j2 = i5[r*5+2], j3 = i5[r*5+3], j4 = i5[r*5+4];

        size_t grow = (size_t)(row0 + r) * D_DIM + h * 256;
        const float4* xp = (const float4*)&x[grow];
        float4*       op = (float4*)&out[grow];
        const float4* c0 = (const float4*)&cc[(size_t)j0 * D_DIM + h * 256];
        const float4* c1 = (const float4*)&cc[(size_t)j1 * D_DIM + h * 256];
        const float4* c2 = (const float4*)&cc[(size_t)j2 * D_DIM + h * 256];
        const float4* c3 = (const float4*)&cc[(size_t)j3 * D_DIM + h * 256];
        const float4* c4 = (const float4*)&cc[(size_t)j4 * D_DIM + h * 256];

        #pragma unroll 4
        for (int q = 0; q < 64; q++) {
            float4 xv = xp[q];
            float4 a0 = c0[q], a1 = c1[q], a2 = c2[q], a3 = c3[q], a4 = c4[q];
            float4 o;
            o.x = xv.x + w0*a0.x + w1*a1.x + w2*a2.x + w3*a3.x + w4*a4.x;
            o.y = xv.y + w0*a0.y + w1*a1.y + w2*a2.y + w3*a3.y + w4*a4.y;
            o.z = xv.z + w0*a0.z + w1*a1.z + w2*a2.z + w3*a3.z + w4*a4.z;
            o.w = xv.w + w0*a0.w + w1*a1.w + w2*a2.w + w3*a3.w + w4*a4.w;
            op[q] = o;
        }
    }
}

extern "C" void kernel_launch(void* const* d_in, const int* in_sizes, int n_in,
                              void* d_out, int out_size)
{
    const float* x  = (const float*)d_in[0];
    const float* cc = (const float*)d_in[1];
    int B = in_sizes[0] / D_DIM;

    cc_split_kernel<<<K_DIM, 256>>>(cc);

    cudaFuncSetAttribute(tse_hmma_kernel, cudaFuncAttributeMaxDynamicSharedMemorySize, SMEM_BYTES);
    tse_hmma_kernel<<<B / BM, NTHR, SMEM_BYTES>>>(x, cc, (float*)d_out);
}

// round 8
// speedup vs baseline: 3.4918x; 1.8210x over previous
#include <cuda_runtime.h>
#include <cuda_fp16.h>
#include <cstdint>

#define D_DIM   512
#define K_DIM   112
#define BM      128
#define NTHR    256
#define NIT     16               // k-chunks of 32
#define LAMBDA_ 5.0f

// SMEM: two A stages (hi+lo), sims overlays afterwards
#define A_STRIDE   80            // bytes per 32-fp16 row (64 data + 16 pad)
#define A_HALF     (BM * A_STRIDE)          // 10240
#define STAGE_B    (2 * A_HALF)             // 20480 (AH + AL)
#define SIMSP      114
#define SIMS_B     (BM * SIMSP * 4)         // 58368
#define W5_OFF     SIMS_B
#define I5_OFF     (W5_OFF + BM * 5 * 4)
#define SMEM_BYTES (I5_OFF + BM * 5 * 4)    // 63488

// B fragment buffers: [kh(32)][p(7)][seg(2)][lane(32)] x uint2
#define FRAG_U2    (32 * 7 * 2 * 32)
__device__ __align__(16) uint2 g_bh[FRAG_U2];
__device__ __align__(16) uint2 g_bl[FRAG_U2];

__device__ __forceinline__ uint32_t smem_u32(const void* p) {
    uint32_t a;
    asm("{ .reg .u64 t; cvta.to.shared.u64 t, %1; cvt.u32.u64 %0, t; }" : "=r"(a) : "l"(p));
    return a;
}
__device__ __forceinline__ void splith(float a, float b, uint32_t& hi, uint32_t& lo) {
    __half2 h = __floats2half2_rn(a, b);
    float2  f = __half22float2(h);
    __half2 l = __floats2half2_rn(a - f.x, b - f.y);
    hi = *(uint32_t*)&h;
    lo = *(uint32_t*)&l;
}

#define LDSM4(r0, r1, r2, r3, addr) \
    asm volatile("ldmatrix.sync.aligned.m8n8.x4.shared.b16 {%0,%1,%2,%3}, [%4];" \
                 : "=r"(r0), "=r"(r1), "=r"(r2), "=r"(r3) : "r"(addr))

#define MMA(d, a0, a1, a2, a3, b0, b1) \
    asm volatile("mma.sync.aligned.m16n8k16.row.col.f32.f16.f16.f32 " \
                 "{%0,%1,%2,%3}, {%4,%5,%6,%7}, {%8,%9}, {%0,%1,%2,%3};" \
                 : "+f"((d)[0]), "+f"((d)[1]), "+f"((d)[2]), "+f"((d)[3]) \
                 : "r"(a0), "r"(a1), "r"(a2), "r"(a3), "r"(b0), "r"(b1))

// ---- pre-kernel: bake C into mma B-fragment order (hi/lo fp16 split) ----
// block = (kh, p); thread t: seg = t>>5, lane = t&31
__global__ void cc_frag_kernel(const float* __restrict__ cc) {
    int kh = blockIdx.x / 7, p = blockIdx.x % 7;
    int t = threadIdx.x, seg = t >> 5, l = t & 31;
    int n  = p * 16 + seg * 8 + (l >> 2);
    int k0 = kh * 16 + (l & 3) * 2;          // b0: (k0, k0+1)
    int k1 = k0 + 8;                          // b1
    uint32_t b0h, b0l, b1h, b1l;
    splith(cc[n * D_DIM + k0], cc[n * D_DIM + k0 + 1], b0h, b0l);
    splith(cc[n * D_DIM + k1], cc[n * D_DIM + k1 + 1], b1h, b1l);
    int idx = ((kh * 7 + p) * 2 + seg) * 32 + l;
    g_bh[idx] = make_uint2(b0h, b1h);
    g_bl[idx] = make_uint2(b0l, b1l);
}

__global__ __launch_bounds__(NTHR, 2)
void tse_hmma2_kernel(const float* __restrict__ x,
                      const float* __restrict__ cc,
                      float* __restrict__ out)
{
    extern __shared__ unsigned char smem[];
    const uint32_t sb = smem_u32(smem);
    const int tid = threadIdx.x;
    const int w   = tid >> 5;
    const int l   = tid & 31;
    const int row0 = blockIdx.x * BM;

    float d[14][4];
    #pragma unroll
    for (int n = 0; n < 14; n++)
        #pragma unroll
        for (int j = 0; j < 4; j++) d[n][j] = 0.0f;

    // ldmatrix A lane offset (within a stage half)
    const uint32_t aOff = (uint32_t)(w * 16 + (l & 15)) * A_STRIDE + ((l >> 4) << 4);

    // x staging mapping: 4 float4 per thread per iteration
    const int srow0 = tid >> 3;          // + 32*i
    const int sseg  = tid & 7;
    float4 px[4];

    auto FETCH = [&](int it) {
        #pragma unroll
        for (int i = 0; i < 4; i++)
            px[i] = *(const float4*)&x[(size_t)(row0 + srow0 + 32 * i) * D_DIM + it * 32 + sseg * 4];
    };
    auto STORE = [&](int s) {
        unsigned char* st = smem + s * STAGE_B;
        #pragma unroll
        for (int i = 0; i < 4; i++) {
            uint32_t h0, l0, h1, l1;
            splith(px[i].x, px[i].y, h0, l0);
            splith(px[i].z, px[i].w, h1, l1);
            uint32_t off = (uint32_t)(srow0 + 32 * i) * A_STRIDE + sseg * 8;
            *(uint2*)(st + off)          = make_uint2(h0, h1);
            *(uint2*)(st + A_HALF + off) = make_uint2(l0, l1);
        }
    };

    const uint2* __restrict__ BH = g_bh;
    const uint2* __restrict__ BL = g_bl;

    FETCH(0);
    for (int it = 0; it < NIT; it++) {
        STORE(it & 1);
        __syncthreads();
        if (it + 1 < NIT) FETCH(it + 1);

        const uint32_t aBase = sb + (it & 1) * STAGE_B + aOff;
        #pragma unroll
        for (int h = 0; h < 2; h++) {
            const int kh = it * 2 + h;
            uint32_t ah0, ah1, ah2, ah3, al0, al1, al2, al3;
            LDSM4(ah0, ah1, ah2, ah3, aBase + h * 32);
            LDSM4(al0, al1, al2, al3, aBase + A_HALF + h * 32);

            uint32_t b[7][4];
            // phase 1: all B-hi fragments (coalesced LDG.64 from L1/L2)
            #pragma unroll
            for (int p = 0; p < 7; p++) {
                uint2 v0 = BH[((kh * 7 + p) * 2 + 0) * 32 + l];
                uint2 v1 = BH[((kh * 7 + p) * 2 + 1) * 32 + l];
                b[p][0] = v0.x; b[p][1] = v0.y; b[p][2] = v1.x; b[p][3] = v1.y;
            }
            #pragma unroll
            for (int p = 0; p < 7; p++) {
                MMA(d[2*p],   ah0, ah1, ah2, ah3, b[p][0], b[p][1]);
                MMA(d[2*p+1], ah0, ah1, ah2, ah3, b[p][2], b[p][3]);
                MMA(d[2*p],   al0, al1, al2, al3, b[p][0], b[p][1]);
                MMA(d[2*p+1], al0, al1, al2, al3, b[p][2], b[p][3]);
            }
            // phase 2: B-lo fragments (reuse regs), hi_x * lo_c term
            #pragma unroll
            for (int p = 0; p < 7; p++) {
                uint2 v0 = BL[((kh * 7 + p) * 2 + 0) * 32 + l];
                uint2 v1 = BL[((kh * 7 + p) * 2 + 1) * 32 + l];
                b[p][0] = v0.x; b[p][1] = v0.y; b[p][2] = v1.x; b[p][3] = v1.y;
            }
            #pragma unroll
            for (int p = 0; p < 7; p++) {
                MMA(d[2*p],   ah0, ah1, ah2, ah3, b[p][0], b[p][1]);
                MMA(d[2*p+1], ah0, ah1, ah2, ah3, b[p][2], b[p][3]);
            }
        }
        __syncthreads();
    }

    // ---- dump sims to smem (overlays A stages) ----
    float* sims = (float*)smem;
    {
        int r1 = w * 16 + (l >> 2);
        int r2 = r1 + 8;
        int c0 = (l & 3) * 2;
        #pragma unroll
        for (int n = 0; n < 14; n++) {
            *(float2*)&sims[r1 * SIMSP + n * 8 + c0] = make_float2(d[n][0], d[n][1]);
            *(float2*)&sims[r2 * SIMSP + n * 8 + c0] = make_float2(d[n][2], d[n][3]);
        }
    }
    __syncthreads();

    // ---- per-row top-5 + softmax ----
    float* w5 = (float*)(smem + W5_OFF);
    int*   i5 = (int*)(smem + I5_OFF);
    if (tid < BM) {
        const float* sr = &sims[tid * SIMSP];
        float v0 = -1e30f, v1 = -1e30f, v2 = -1e30f, v3 = -1e30f, v4 = -1e30f;
        int   i0 = 0, i1 = 0, i2 = 0, i3 = 0, i4 = 0;
        for (int c = 0; c < K_DIM; c++) {
            float s = sr[c];
            if (s > v4) {                       // strict >: earliest index wins ties
                v4 = s; i4 = c;
                if (v4 > v3) { float t=v3; v3=v4; v4=t; int q=i3; i3=i4; i4=q; }
                if (v3 > v2) { float t=v2; v2=v3; v3=t; int q=i2; i2=i3; i3=q; }
                if (v2 > v1) { float t=v1; v1=v2; v2=t; int q=i1; i1=i2; i2=q; }
                if (v1 > v0) { float t=v0; v0=v1; v1=t; int q=i0; i0=i1; i1=q; }
            }
        }
        float e1 = __expf(v1 - v0);
        float e2 = __expf(v2 - v0);
        float e3 = __expf(v3 - v0);
        float e4 = __expf(v4 - v0);
        float inv = LAMBDA_ / (1.0f + e1 + e2 + e3 + e4);
        w5[tid*5+0] = inv;      i5[tid*5+0] = i0;
        w5[tid*5+1] = e1 * inv; i5[tid*5+1] = i1;
        w5[tid*5+2] = e2 * inv; i5[tid*5+2] = i2;
        w5[tid*5+3] = e3 * inv; i5[tid*5+3] = i3;
        w5[tid*5+4] = e4 * inv; i5[tid*5+4] = i4;
    }
    __syncthreads();

    // ---- epilogue: warp-per-row, fully coalesced ----
    #pragma unroll 1
    for (int rr = 0; rr < 16; rr++) {
        int r = w * 16 + rr;
        float w0 = w5[r*5+0], w1 = w5[r*5+1], w2 = w5[r*5+2], w3 = w5[r*5+3], w4 = w5[r*5+4];
        int   j0 = i5[r*5+0], j1 = i5[r*5+1], j2 = i5[r*5+2], j3 = i5[r*5+3], j4 = i5[r*5+4];

        const float4* xp = (const float4*)&x[(size_t)(row0 + r) * D_DIM];
        float4*       op = (float4*)&out[(size_t)(row0 + r) * D_DIM];
        const float4* c0 = (const float4*)&cc[(size_t)j0 * D_DIM];
        const float4* c1 = (const float4*)&cc[(size_t)j1 * D_DIM];
        const float4* c2 = (const float4*)&cc[(size_t)j2 * D_DIM];
        const float4* c3 = (const float4*)&cc[(size_t)j3 * D_DIM];
        const float4* c4 = (const float4*)&cc[(size_t)j4 * D_DIM];

        #pragma unroll
        for (int i = 0; i < 4; i++) {
            int q = l + 32 * i;
            float4 xv = xp[q];
            float4 a0 = c0[q], a1 = c1[q], a2 = c2[q], a3 = c3[q], a4 = c4[q];
            float4 o;
            o.x = xv.x + w0*a0.x + w1*a1.x + w2*a2.x + w3*a3.x + w4*a4.x;
            o.y = xv.y + w0*a0.y + w1*a1.y + w2*a2.y + w3*a3.y + w4*a4.y;
            o.z = xv.z + w0*a0.z + w1*a1.z + w2*a2.z + w3*a3.z + w4*a4.z;
            o.w = xv.w + w0*a0.w + w1*a1.w + w2*a2.w + w3*a3.w + w4*a4.w;
            op[q] = o;
        }
    }
}

extern "C" void kernel_launch(void* const* d_in, const int* in_sizes, int n_in,
                              void* d_out, int out_size)
{
    const float* x  = (const float*)d_in[0];
    const float* cc = (const float*)d_in[1];
    int B = in_sizes[0] / D_DIM;

    cc_frag_kernel<<<32 * 7, 64>>>(cc);

    cudaFuncSetAttribute(tse_hmma2_kernel, cudaFuncAttributeMaxDynamicSharedMemorySize, SMEM_BYTES);
    tse_hmma2_kernel<<<B / BM, NTHR, SMEM_BYTES>>>(x, cc, (float*)d_out);
}